// round 2
// baseline (speedup 1.0000x reference)
#include <cuda_runtime.h>
#include <math.h>

// Problem constants
constexpr int SEQ  = 2048;
constexpr int DIM  = 2048;
constexpr int NHEADS = 16;
constexpr int NKV    = 4;
constexpr int HDIM   = 128;
constexpr int FFD    = 8192;
constexpr float EPSV = 1e-6f;

// ---------------------------------------------------------------------------
// Scratch buffers (device globals — no allocation allowed)
// ---------------------------------------------------------------------------
__device__ float g_h1[(long)SEQ * DIM];
__device__ float g_q [(long)SEQ * NHEADS * HDIM];
__device__ float g_k [(long)SEQ * NKV * HDIM];
__device__ float g_v [(long)SEQ * NKV * HDIM];
__device__ float g_sc[(long)NHEADS * SEQ * SEQ];   // scores -> probs (256 MB)
__device__ float g_at[(long)SEQ * NHEADS * HDIM];  // attn output [S, H*HD]
__device__ float g_x2[(long)SEQ * DIM];
__device__ float g_h2[(long)SEQ * DIM];
__device__ float g_g [(long)SEQ * FFD];            // gate proj
__device__ float g_m [(long)SEQ * FFD];            // silu(g)*u

// ---------------------------------------------------------------------------
// RMSNorm: one block per row
// ---------------------------------------------------------------------------
__global__ __launch_bounds__(256)
void rmsnorm_kernel(const float* __restrict__ x, const float* __restrict__ w,
                    float* __restrict__ o)
{
    const int row = blockIdx.x;
    const float* xr = x + (long)row * DIM;
    float s = 0.f;
    for (int j = threadIdx.x; j < DIM; j += 256) {
        float v = xr[j];
        s += v * v;
    }
    __shared__ float red[256];
    red[threadIdx.x] = s;
    __syncthreads();
    for (int st = 128; st > 0; st >>= 1) {
        if (threadIdx.x < st) red[threadIdx.x] += red[threadIdx.x + st];
        __syncthreads();
    }
    const float inv = rsqrtf(red[0] * (1.0f / DIM) + EPSV);
    float* orow = o + (long)row * DIM;
    for (int j = threadIdx.x; j < DIM; j += 256)
        orow[j] = xr[j] * inv * w[j];
}

// ---------------------------------------------------------------------------
// RoPE in-place on q [S, H*HD] and k [S, KVH*HD]. 64 threads = 64 dim pairs.
// blockIdx.x = seq pos, blockIdx.y = head index (0..NHEADS-1 -> q, rest -> k)
// ---------------------------------------------------------------------------
__global__ void rope_kernel(float* __restrict__ q, float* __restrict__ k)
{
    const int s = blockIdx.x;
    const int h = blockIdx.y;
    const int d = threadIdx.x;  // 0..63
    float* base = (h < NHEADS)
        ? (q + (long)s * (NHEADS * HDIM) + h * HDIM)
        : (k + (long)s * (NKV * HDIM) + (h - NHEADS) * HDIM);
    const double ang = (double)s * pow(10000.0, -(double)d / 64.0);
    const float c  = (float)cos(ang);
    const float sn = (float)sin(ang);
    const float x0 = base[d];
    const float x1 = base[d + 64];
    base[d]      = x0 * c - x1 * sn;   // rotate_half: first half uses -x[d+64]
    base[d + 64] = x1 * c + x0 * sn;   // second half uses +x[d]
}

// ---------------------------------------------------------------------------
// Causal softmax over scores row. Writes probs (zeros above the diagonal).
// blockIdx.x = query row, blockIdx.y = head
// ---------------------------------------------------------------------------
__global__ __launch_bounds__(256)
void softmax_kernel(float* __restrict__ scores)
{
    const int srow = blockIdx.x;
    const int h    = blockIdx.y;
    float* row = scores + ((long)h * SEQ + srow) * SEQ;
    const int n = srow + 1;

    __shared__ float buf[SEQ];
    __shared__ float red[256];
    const int tid = threadIdx.x;

    float mx = -1e30f;
    for (int j = tid; j < n; j += 256) {
        float v = row[j];
        buf[j] = v;
        mx = fmaxf(mx, v);
    }
    red[tid] = mx;
    __syncthreads();
    for (int st = 128; st > 0; st >>= 1) {
        if (tid < st) red[tid] = fmaxf(red[tid], red[tid + st]);
        __syncthreads();
    }
    mx = red[0];
    __syncthreads();

    float sum = 0.f;
    for (int j = tid; j < n; j += 256) {
        float e = expf(buf[j] - mx);
        buf[j] = e;
        sum += e;
    }
    red[tid] = sum;
    __syncthreads();
    for (int st = 128; st > 0; st >>= 1) {
        if (tid < st) red[tid] += red[tid + st];
        __syncthreads();
    }
    const float inv = 1.0f / red[0];
    for (int j = tid; j < SEQ; j += 256)
        row[j] = (j < n) ? buf[j] * inv : 0.0f;
}

// ---------------------------------------------------------------------------
// Generic tiled fp32 GEMM: C[M,N] = op(A[M,K] x B), batched via blockIdx.z.
//   BT=false: B row-major [K,N]   BT=true: B row-major [N,K] (i.e. A x B^T)
// Epilogue modes:
//   0 NONE   : C = acc
//   1 RESID  : C = acc + Aux      (Aux addressed like C)
//   2 SCORES : if (col<=row) C = acc*scale  (causal; skips masked writes)
//   3 SILU   : C = silu(Aux) * acc
// Batch: A += z*sA; B += (z/bGroup)*sB; C += z*sC  (GQA via bGroup)
// Block: 128x128, BK=8, 256 threads, 8x8 per thread.
// Requires M%128==0, N%128==0, K%8==0 (true for all calls here).
// ---------------------------------------------------------------------------
template<int MODE, bool BT>
__global__ __launch_bounds__(256)
void gemm_kernel(const float* __restrict__ A, const float* __restrict__ B,
                 float* __restrict__ C, const float* __restrict__ Aux,
                 int M, int N, int K, int lda, int ldb, int ldc,
                 long sA, long sB, long sC, int bGroup, float scale)
{
    const int bz = blockIdx.z;
    A += (long)bz * sA;
    B += (long)(bz / bGroup) * sB;
    C += (long)bz * sC;

    const int row0 = blockIdx.y * 128;
    const int col0 = blockIdx.x * 128;
    if (MODE == 2 && col0 > row0 + 127) return;  // fully-masked tile

    __shared__ float As[8][128];
    __shared__ float Bs[8][128];

    const int tid  = threadIdx.x;
    const int aRow = tid >> 1;          // 0..127
    const int aCol = (tid & 1) << 2;    // 0 or 4
    const int bRow = tid >> 5;          // 0..7   (NN B load)
    const int bCol = (tid & 31) << 2;   // 0..124
    const int ty   = tid >> 4;          // 0..15
    const int tx   = tid & 15;          // 0..15

    float acc[8][8];
#pragma unroll
    for (int i = 0; i < 8; i++)
#pragma unroll
        for (int j = 0; j < 8; j++) acc[i][j] = 0.f;

    for (int k0 = 0; k0 < K; k0 += 8) {
        float4 av = *(const float4*)(A + (long)(row0 + aRow) * lda + k0 + aCol);
        As[aCol + 0][aRow] = av.x;
        As[aCol + 1][aRow] = av.y;
        As[aCol + 2][aRow] = av.z;
        As[aCol + 3][aRow] = av.w;
        if (BT) {
            float4 bv = *(const float4*)(B + (long)(col0 + aRow) * ldb + k0 + aCol);
            Bs[aCol + 0][aRow] = bv.x;
            Bs[aCol + 1][aRow] = bv.y;
            Bs[aCol + 2][aRow] = bv.z;
            Bs[aCol + 3][aRow] = bv.w;
        } else {
            float4 bv = *(const float4*)(B + (long)(k0 + bRow) * ldb + col0 + bCol);
            *(float4*)(&Bs[bRow][bCol]) = bv;
        }
        __syncthreads();

#pragma unroll
        for (int kk = 0; kk < 8; kk++) {
            float ra[8], rb[8];
#pragma unroll
            for (int i = 0; i < 8; i++) ra[i] = As[kk][ty * 8 + i];
#pragma unroll
            for (int j = 0; j < 8; j++) rb[j] = Bs[kk][tx * 8 + j];
#pragma unroll
            for (int i = 0; i < 8; i++)
#pragma unroll
                for (int j = 0; j < 8; j++)
                    acc[i][j] = fmaf(ra[i], rb[j], acc[i][j]);
        }
        __syncthreads();
    }

#pragma unroll
    for (int i = 0; i < 8; i++) {
        const int r = row0 + ty * 8 + i;
#pragma unroll
        for (int j = 0; j < 8; j++) {
            const int c = col0 + tx * 8 + j;
            const long idx = (long)r * ldc + c;
            if (MODE == 0) {
                C[idx] = acc[i][j];
            } else if (MODE == 1) {
                C[idx] = acc[i][j] + Aux[idx];
            } else if (MODE == 2) {
                if (c <= r) C[idx] = acc[i][j] * scale;
            } else {  // MODE == 3
                float gv = Aux[idx];
                C[idx] = (gv / (1.f + expf(-gv))) * acc[i][j];
            }
        }
    }
}

// ---------------------------------------------------------------------------
// kernel_launch
// Inputs: 0 hidden_states, 1 attention_mask (ignored: exactly causal),
// 2 ln1_w, 3 Wq, 4 Wk, 5 Wv, 6 Wo, 7 ln2_w, 8 Wg, 9 Wu, 10 Wd
// ---------------------------------------------------------------------------
extern "C" void kernel_launch(void* const* d_in, const int* in_sizes, int n_in,
                              void* d_out, int out_size)
{
    (void)in_sizes; (void)n_in; (void)out_size;
    const float* x   = (const float*)d_in[0];
    const float* ln1 = (const float*)d_in[2];
    const float* Wq  = (const float*)d_in[3];
    const float* Wk  = (const float*)d_in[4];
    const float* Wv  = (const float*)d_in[5];
    const float* Wo  = (const float*)d_in[6];
    const float* ln2 = (const float*)d_in[7];
    const float* Wg  = (const float*)d_in[8];
    const float* Wu  = (const float*)d_in[9];
    const float* Wd  = (const float*)d_in[10];
    float* out = (float*)d_out;

    float *h1, *q, *k, *v, *sc, *at, *x2, *h2, *gg, *mm;
    cudaGetSymbolAddress((void**)&h1, g_h1);
    cudaGetSymbolAddress((void**)&q,  g_q);
    cudaGetSymbolAddress((void**)&k,  g_k);
    cudaGetSymbolAddress((void**)&v,  g_v);
    cudaGetSymbolAddress((void**)&sc, g_sc);
    cudaGetSymbolAddress((void**)&at, g_at);
    cudaGetSymbolAddress((void**)&x2, g_x2);
    cudaGetSymbolAddress((void**)&h2, g_h2);
    cudaGetSymbolAddress((void**)&gg, g_g);
    cudaGetSymbolAddress((void**)&mm, g_m);

    const float iscale = 0.08838834764831843f;  // 1/sqrt(128)

    // 1) h1 = rmsnorm(x)
    rmsnorm_kernel<<<SEQ, 256>>>(x, ln1, h1);

    // 2) q,k,v projections
    gemm_kernel<0, false><<<dim3(DIM / 128, SEQ / 128, 1), 256>>>(
        h1, Wq, q, nullptr, SEQ, NHEADS * HDIM, DIM, DIM, NHEADS * HDIM,
        NHEADS * HDIM, 0, 0, 0, 1, 1.f);
    gemm_kernel<0, false><<<dim3((NKV * HDIM) / 128, SEQ / 128, 1), 256>>>(
        h1, Wk, k, nullptr, SEQ, NKV * HDIM, DIM, DIM, NKV * HDIM,
        NKV * HDIM, 0, 0, 0, 1, 1.f);
    gemm_kernel<0, false><<<dim3((NKV * HDIM) / 128, SEQ / 128, 1), 256>>>(
        h1, Wv, v, nullptr, SEQ, NKV * HDIM, DIM, DIM, NKV * HDIM,
        NKV * HDIM, 0, 0, 0, 1, 1.f);

    // 3) RoPE on q and k (20 = 16 q-heads + 4 kv-heads)
    rope_kernel<<<dim3(SEQ, NHEADS + NKV), 64>>>(q, k);

    // 4) scores[h] = causal( (q_h @ k_{h/4}^T) / sqrt(HD) )
    gemm_kernel<2, true><<<dim3(SEQ / 128, SEQ / 128, NHEADS), 256>>>(
        q, k, sc, nullptr, SEQ, SEQ, HDIM,
        NHEADS * HDIM, NKV * HDIM, SEQ,
        (long)HDIM, (long)HDIM, (long)SEQ * SEQ, NKV, iscale);

    // 5) softmax (writes zeros above diagonal)
    softmax_kernel<<<dim3(SEQ, NHEADS), 256>>>(sc);

    // 6) attn[h] = probs_h @ v_{h/4}, written to [S, H*HD]
    gemm_kernel<0, false><<<dim3(HDIM / 128, SEQ / 128, NHEADS), 256>>>(
        sc, v, at, nullptr, SEQ, HDIM, SEQ,
        SEQ, NKV * HDIM, NHEADS * HDIM,
        (long)SEQ * SEQ, (long)HDIM, (long)HDIM, NKV, 1.f);

    // 7) x2 = attn @ Wo + x
    gemm_kernel<1, false><<<dim3(DIM / 128, SEQ / 128, 1), 256>>>(
        at, Wo, x2, x, SEQ, DIM, NHEADS * HDIM,
        NHEADS * HDIM, DIM, DIM, 0, 0, 0, 1, 1.f);

    // 8) h2 = rmsnorm(x2)
    rmsnorm_kernel<<<SEQ, 256>>>(x2, ln2, h2);

    // 9) g = h2 @ Wg
    gemm_kernel<0, false><<<dim3(FFD / 128, SEQ / 128, 1), 256>>>(
        h2, Wg, gg, nullptr, SEQ, FFD, DIM, DIM, FFD, FFD, 0, 0, 0, 1, 1.f);

    // 10) m = silu(g) * (h2 @ Wu)
    gemm_kernel<3, false><<<dim3(FFD / 128, SEQ / 128, 1), 256>>>(
        h2, Wu, mm, gg, SEQ, FFD, DIM, DIM, FFD, FFD, 0, 0, 0, 1, 1.f);

    // 11) out = m @ Wd + x2
    gemm_kernel<1, false><<<dim3(DIM / 128, SEQ / 128, 1), 256>>>(
        mm, Wd, out, x2, SEQ, DIM, FFD, FFD, DIM, DIM, 0, 0, 0, 1, 1.f);
}

// round 4
// speedup vs baseline: 3.8236x; 3.8236x over previous
#include <cuda_runtime.h>
#include <cstdint>
#include <math.h>

constexpr int SEQ = 2048, DIM = 2048, NH = 16, NKV = 4, HD = 128, FF = 8192;
constexpr float EPSV = 1e-6f;

// ---------------------------------------------------------------------------
// Scratch (device globals — allocation forbidden)
// ---------------------------------------------------------------------------
__device__ float g_h1[SEQ * DIM];
__device__ float g_q [SEQ * NH * HD];
__device__ float g_k [SEQ * NKV * HD];
__device__ float g_v [SEQ * NKV * HD];
__device__ float g_vT[NKV * HD * SEQ];
__device__ float g_sc[(long)NH * SEQ * SEQ];
__device__ float g_at[SEQ * NH * HD];
__device__ float g_x2[SEQ * DIM];
__device__ float g_h2[SEQ * DIM];
__device__ float g_gg[(long)SEQ * FF];
__device__ float g_mm[(long)SEQ * FF];
__device__ float g_WqT[DIM * DIM];
__device__ float g_WkT[NKV * HD * DIM];
__device__ float g_WvT[NKV * HD * DIM];
__device__ float g_WoT[DIM * DIM];
__device__ float g_WgT[(long)FF * DIM];
__device__ float g_WuT[(long)FF * DIM];
__device__ float g_WdT[(long)DIM * FF];
__device__ double g_invf[64];
__device__ float2 g_cs[SEQ * 64];

// ---------------------------------------------------------------------------
__device__ __forceinline__ uint32_t smem_u32(const void* p) {
    uint32_t a;
    asm("{ .reg .u64 t; cvta.to.shared.u64 t, %1; cvt.u32.u64 %0, t; }" : "=r"(a) : "l"(p));
    return a;
}
__device__ __forceinline__ float to_tf32(float x) {
    uint32_t u;
    asm("cvt.rna.tf32.f32 %0, %1;" : "=r"(u) : "f"(x));
    return __uint_as_float(u);
}
__device__ __forceinline__ void cp16(uint32_t dst, const void* src) {
    asm volatile("cp.async.cg.shared.global [%0], [%1], 16;" :: "r"(dst), "l"(src) : "memory");
}
__device__ __forceinline__ void cp_commit() {
    asm volatile("cp.async.commit_group;" ::: "memory");
}
template<int N> __device__ __forceinline__ void cp_wait() {
    asm volatile("cp.async.wait_group %0;" :: "n"(N) : "memory");
}
__device__ __forceinline__ void mma_tf32(float* c, const uint32_t* a, const uint32_t* b) {
    asm volatile(
        "mma.sync.aligned.m16n8k8.row.col.f32.tf32.tf32.f32 "
        "{%0,%1,%2,%3}, {%4,%5,%6,%7}, {%8,%9}, {%0,%1,%2,%3};"
        : "+f"(c[0]), "+f"(c[1]), "+f"(c[2]), "+f"(c[3])
        : "r"(a[0]), "r"(a[1]), "r"(a[2]), "r"(a[3]), "r"(b[0]), "r"(b[1]));
}

__device__ __forceinline__ float fexp(float x) {  // accurate for x <= 0
    float t = x * 1.4426950408889634f;
    float r = rintf(t), f = t - r;
    int i = (int)r;
    float p = 0.0013333558f;
    p = fmaf(p, f, 0.0096181291f);
    p = fmaf(p, f, 0.0555041087f);
    p = fmaf(p, f, 0.2402264476f);
    p = fmaf(p, f, 0.6931471806f);
    p = fmaf(p, f, 1.0f);
    float s = __int_as_float((i + 127) << 23);
    return (x < -80.f) ? 0.f : p * s;
}
__device__ __forceinline__ float silu(float g) {
    float t = fexp(-fabsf(g));
    float s = (g >= 0.f) ? 1.f / (1.f + t) : t / (1.f + t);
    return g * s;
}

// ---------------- transpose + round to tf32: out[N,K] = rna(in[K,N]^T) -----
__global__ __launch_bounds__(256)
void transpose_round(const float* __restrict__ in, float* __restrict__ out, int K, int N) {
    __shared__ float tb[32][33];
    const int kb = blockIdx.y * 32, nb = blockIdx.x * 32;
    const int tx = threadIdx.x & 31, ty4 = threadIdx.x >> 5;
#pragma unroll
    for (int i = 0; i < 4; i++) {
        int r = ty4 * 4 + i;
        tb[r][tx] = to_tf32(in[(size_t)(kb + r) * N + nb + tx]);
    }
    __syncthreads();
#pragma unroll
    for (int i = 0; i < 4; i++) {
        int r = ty4 * 4 + i;
        out[(size_t)(nb + r) * K + kb + tx] = tb[tx][r];
    }
}

// ---------------- rmsnorm (tf32-rounded out) -------------------------------
__global__ __launch_bounds__(256)
void rmsnorm_kernel(const float* __restrict__ x, const float* __restrict__ w,
                    float* __restrict__ o) {
    const int row = blockIdx.x;
    const float* xr = x + (size_t)row * DIM;
    float s = 0.f;
    for (int j = threadIdx.x; j < DIM; j += 256) { float v = xr[j]; s += v * v; }
    __shared__ float red[256];
    red[threadIdx.x] = s;
    __syncthreads();
    for (int st = 128; st > 0; st >>= 1) {
        if (threadIdx.x < st) red[threadIdx.x] += red[threadIdx.x + st];
        __syncthreads();
    }
    const float inv = rsqrtf(red[0] * (1.0f / DIM) + EPSV);
    float* orow = o + (size_t)row * DIM;
    for (int j = threadIdx.x; j < DIM; j += 256)
        orow[j] = to_tf32(xr[j] * inv * w[j]);
}

// ---------------- RoPE -----------------------------------------------------
__global__ void init_invf_kernel() { g_invf[threadIdx.x] = pow(10000.0, -(double)threadIdx.x / 64.0); }
__global__ void rope_table_kernel() {
    int s = blockIdx.x, d = threadIdx.x;
    double ang = (double)s * g_invf[d];
    const double twopi = 6.283185307179586476925287;
    double r = ang - twopi * floor(ang / twopi + 0.5);
    float rf = (float)r;
    g_cs[s * 64 + d] = make_float2(cosf(rf), sinf(rf));
}
__global__ void rope_apply_kernel(float* __restrict__ q, float* __restrict__ k) {
    const int s = blockIdx.x, h = blockIdx.y, d = threadIdx.x;
    float* base = (h < NH) ? (q + (size_t)s * (NH * HD) + h * HD)
                           : (k + (size_t)s * (NKV * HD) + (h - NH) * HD);
    float2 cs = g_cs[s * 64 + d];
    float x0 = base[d], x1 = base[d + 64];
    base[d]      = to_tf32(x0 * cs.x - x1 * cs.y);
    base[d + 64] = to_tf32(x1 * cs.x + x0 * cs.y);
}

// ---------------- softmax (tf32 probs, zero-pad to 128 boundary) -----------
__global__ __launch_bounds__(256)
void softmax_kernel(float* __restrict__ scores) {
    const int srow = blockIdx.x, h = blockIdx.y;
    float* row = scores + ((size_t)h * SEQ + srow) * SEQ;
    const int n = srow + 1;
    const int padn = ((n + 127) / 128) * 128;
    __shared__ float buf[SEQ];
    __shared__ float red[256];
    const int tid = threadIdx.x;
    float mx = -1e30f;
    for (int j = tid; j < n; j += 256) { float v = row[j]; buf[j] = v; mx = fmaxf(mx, v); }
    red[tid] = mx;
    __syncthreads();
    for (int st = 128; st > 0; st >>= 1) {
        if (tid < st) red[tid] = fmaxf(red[tid], red[tid + st]);
        __syncthreads();
    }
    mx = red[0];
    __syncthreads();
    float sum = 0.f;
    for (int j = tid; j < n; j += 256) { float e = fexp(buf[j] - mx); buf[j] = e; sum += e; }
    red[tid] = sum;
    __syncthreads();
    for (int st = 128; st > 0; st >>= 1) {
        if (tid < st) red[tid] += red[tid + st];
        __syncthreads();
    }
    const float inv = 1.0f / red[0];
    for (int j = tid; j < padn; j += 256)
        row[j] = (j < n) ? to_tf32(buf[j] * inv) : 0.0f;
}

// ---------------------------------------------------------------------------
// mma.sync tf32 GEMM: C[M,N] = A[M,K] @ B[N,K]^T (both K-major, tf32-rounded).
// BM=128, BN=128, BK=32, 256 threads (8 warps, 2x4), warp tile 64x32.
// EPI: 0 fp32 store, 1 +Aux, 2 *scale causal, 3 tf32(silu(Aux)*acc), 4 tf32.
// Batch z: A += z*zA, B += (z/bGroup)*zB, C/Aux += z*zC.
// CK: K-loop truncated at row0+128 (causal PV).
// ---------------------------------------------------------------------------
constexpr int TS = 36;                  // smem row stride (floats)
constexpr int BUFSZ = 128 * TS;         // one tile buffer
constexpr int GEMM_SMEM = 4 * BUFSZ * 4;  // A0,A1,B0,B1 in bytes

template<int EPI, bool CAUSAL, bool CK>
__global__ __launch_bounds__(256)
void mma_gemm(const float* __restrict__ A, const float* __restrict__ B,
              float* __restrict__ C, const float* __restrict__ Aux,
              int K, int lda, int ldb, int ldc,
              long zA, long zB, long zC, int bGroup, float scale) {
    const int row0 = blockIdx.y * 128;
    const int col0 = blockIdx.x * 128;
    if (CAUSAL && col0 > row0 + 127) return;
    const int bz = blockIdx.z;
    A += (size_t)bz * zA;
    B += (size_t)(bz / bGroup) * zB;
    C += (size_t)bz * zC;
    if (EPI == 1 || EPI == 3) Aux += (size_t)bz * zC;

    extern __shared__ float sm[];
    const uint32_t smBase = smem_u32(sm);

    const int tid = threadIdx.x;
    const int wid = tid >> 5, lane = tid & 31;
    const int lr = lane >> 2, lc = lane & 3;
    const int wm = (wid & 1) * 64;     // warp row offset in tile
    const int wn = (wid >> 1) * 32;    // warp col offset in tile

    const int nkt = CK ? (row0 + 128) / 32 : K / 32;

    // staging: tile kt -> buffer buf (A and B, 8 cp.async/thread)
    auto stage = [&](int buf, int kt) {
        const float* Ap = A + (size_t)row0 * lda + kt * 32;
        const float* Bp = B + (size_t)col0 * ldb + kt * 32;
        const uint32_t aB = smBase + (uint32_t)buf * BUFSZ * 4;
        const uint32_t bB = smBase + (uint32_t)(2 + buf) * BUFSZ * 4;
#pragma unroll
        for (int j = 0; j < 4; j++) {
            int idx = j * 256 + tid, r = idx >> 3, c4 = idx & 7;
            cp16(aB + (uint32_t)(r * TS + c4 * 4) * 4, Ap + (size_t)r * lda + c4 * 4);
        }
#pragma unroll
        for (int j = 0; j < 4; j++) {
            int idx = j * 256 + tid, r = idx >> 3, c4 = idx & 7;
            cp16(bB + (uint32_t)(r * TS + c4 * 4) * 4, Bp + (size_t)r * ldb + c4 * 4);
        }
    };

    float acc[4][4][4];
#pragma unroll
    for (int mt = 0; mt < 4; mt++)
#pragma unroll
        for (int nt = 0; nt < 4; nt++)
#pragma unroll
            for (int i = 0; i < 4; i++) acc[mt][nt][i] = 0.f;

    stage(0, 0);
    cp_commit();

    for (int kt = 0; kt < nkt; kt++) {
        if (kt + 1 < nkt) { stage((kt + 1) & 1, kt + 1); cp_commit(); cp_wait<1>(); }
        else              { cp_wait<0>(); }
        __syncthreads();

        const float* a_s = sm + (kt & 1) * BUFSZ;
        const float* b_s = sm + (2 + (kt & 1)) * BUFSZ;
#pragma unroll
        for (int ks = 0; ks < 4; ks++) {
            uint32_t af[4][4], bf[4][2];
            const int kb = ks * 8 + lc;
#pragma unroll
            for (int mt = 0; mt < 4; mt++) {
                const int r = wm + mt * 16 + lr;
                af[mt][0] = __float_as_uint(a_s[r * TS + kb]);
                af[mt][1] = __float_as_uint(a_s[(r + 8) * TS + kb]);
                af[mt][2] = __float_as_uint(a_s[r * TS + kb + 4]);
                af[mt][3] = __float_as_uint(a_s[(r + 8) * TS + kb + 4]);
            }
#pragma unroll
            for (int nt = 0; nt < 4; nt++) {
                const int c = wn + nt * 8 + lr;
                bf[nt][0] = __float_as_uint(b_s[c * TS + kb]);
                bf[nt][1] = __float_as_uint(b_s[c * TS + kb + 4]);
            }
#pragma unroll
            for (int mt = 0; mt < 4; mt++)
#pragma unroll
                for (int nt = 0; nt < 4; nt++)
                    mma_tf32(acc[mt][nt], af[mt], bf[nt]);
        }
        __syncthreads();
    }

    // -------- epilogue: each thread owns, per (mt,nt): rows r,r+8; cols c,c+1
#pragma unroll
    for (int mt = 0; mt < 4; mt++) {
        const int ra = row0 + wm + mt * 16 + lr;
        const int rb = ra + 8;
#pragma unroll
        for (int nt = 0; nt < 4; nt++) {
            const int c = col0 + wn + nt * 8 + lc * 2;
            float* acc4 = acc[mt][nt];
            const size_t ia = (size_t)ra * ldc + c;
            const size_t ib = (size_t)rb * ldc + c;
            if (EPI == 0) {
                *(float2*)&C[ia] = make_float2(acc4[0], acc4[1]);
                *(float2*)&C[ib] = make_float2(acc4[2], acc4[3]);
            } else if (EPI == 1) {
                float2 xa = *(const float2*)&Aux[ia], xb = *(const float2*)&Aux[ib];
                *(float2*)&C[ia] = make_float2(acc4[0] + xa.x, acc4[1] + xa.y);
                *(float2*)&C[ib] = make_float2(acc4[2] + xb.x, acc4[3] + xb.y);
            } else if (EPI == 2) {
                if (c     <= ra) C[ia]     = acc4[0] * scale;
                if (c + 1 <= ra) C[ia + 1] = acc4[1] * scale;
                if (c     <= rb) C[ib]     = acc4[2] * scale;
                if (c + 1 <= rb) C[ib + 1] = acc4[3] * scale;
            } else if (EPI == 3) {
                float2 ga = *(const float2*)&Aux[ia], gb = *(const float2*)&Aux[ib];
                *(float2*)&C[ia] = make_float2(to_tf32(acc4[0] * silu(ga.x)),
                                               to_tf32(acc4[1] * silu(ga.y)));
                *(float2*)&C[ib] = make_float2(to_tf32(acc4[2] * silu(gb.x)),
                                               to_tf32(acc4[3] * silu(gb.y)));
            } else {  // EPI == 4
                *(float2*)&C[ia] = make_float2(to_tf32(acc4[0]), to_tf32(acc4[1]));
                *(float2*)&C[ib] = make_float2(to_tf32(acc4[2]), to_tf32(acc4[3]));
            }
        }
    }
}

// ---------------------------------------------------------------------------
extern "C" void kernel_launch(void* const* d_in, const int* in_sizes, int n_in,
                              void* d_out, int out_size) {
    (void)in_sizes; (void)n_in; (void)out_size;
    const float* x   = (const float*)d_in[0];
    const float* ln1 = (const float*)d_in[2];
    const float* Wq  = (const float*)d_in[3];
    const float* Wk  = (const float*)d_in[4];
    const float* Wv  = (const float*)d_in[5];
    const float* Wo  = (const float*)d_in[6];
    const float* ln2 = (const float*)d_in[7];
    const float* Wg  = (const float*)d_in[8];
    const float* Wu  = (const float*)d_in[9];
    const float* Wd  = (const float*)d_in[10];
    float* out = (float*)d_out;

    float *h1, *q, *k, *v, *vT, *sc, *at, *x2, *h2, *gg, *mm;
    float *WqT, *WkT, *WvT, *WoT, *WgT, *WuT, *WdT;
    cudaGetSymbolAddress((void**)&h1, g_h1);   cudaGetSymbolAddress((void**)&q, g_q);
    cudaGetSymbolAddress((void**)&k, g_k);     cudaGetSymbolAddress((void**)&v, g_v);
    cudaGetSymbolAddress((void**)&vT, g_vT);   cudaGetSymbolAddress((void**)&sc, g_sc);
    cudaGetSymbolAddress((void**)&at, g_at);   cudaGetSymbolAddress((void**)&x2, g_x2);
    cudaGetSymbolAddress((void**)&h2, g_h2);   cudaGetSymbolAddress((void**)&gg, g_gg);
    cudaGetSymbolAddress((void**)&mm, g_mm);
    cudaGetSymbolAddress((void**)&WqT, g_WqT); cudaGetSymbolAddress((void**)&WkT, g_WkT);
    cudaGetSymbolAddress((void**)&WvT, g_WvT); cudaGetSymbolAddress((void**)&WoT, g_WoT);
    cudaGetSymbolAddress((void**)&WgT, g_WgT); cudaGetSymbolAddress((void**)&WuT, g_WuT);
    cudaGetSymbolAddress((void**)&WdT, g_WdT);

    cudaFuncSetAttribute(mma_gemm<0, false, false>, cudaFuncAttributeMaxDynamicSharedMemorySize, GEMM_SMEM);
    cudaFuncSetAttribute(mma_gemm<1, false, false>, cudaFuncAttributeMaxDynamicSharedMemorySize, GEMM_SMEM);
    cudaFuncSetAttribute(mma_gemm<2, true,  false>, cudaFuncAttributeMaxDynamicSharedMemorySize, GEMM_SMEM);
    cudaFuncSetAttribute(mma_gemm<3, false, false>, cudaFuncAttributeMaxDynamicSharedMemorySize, GEMM_SMEM);
    cudaFuncSetAttribute(mma_gemm<4, false, true >, cudaFuncAttributeMaxDynamicSharedMemorySize, GEMM_SMEM);

    const float iscale = 0.08838834764831843f;  // 1/sqrt(128)

    // weight transposes (+ tf32 rounding) and RoPE tables
    transpose_round<<<dim3(DIM / 32, DIM / 32), 256>>>(Wq, WqT, DIM, DIM);
    transpose_round<<<dim3(512 / 32, DIM / 32), 256>>>(Wk, WkT, DIM, 512);
    transpose_round<<<dim3(512 / 32, DIM / 32), 256>>>(Wv, WvT, DIM, 512);
    transpose_round<<<dim3(DIM / 32, DIM / 32), 256>>>(Wo, WoT, DIM, DIM);
    transpose_round<<<dim3(FF / 32, DIM / 32), 256>>>(Wg, WgT, DIM, FF);
    transpose_round<<<dim3(FF / 32, DIM / 32), 256>>>(Wu, WuT, DIM, FF);
    transpose_round<<<dim3(DIM / 32, FF / 32), 256>>>(Wd, WdT, FF, DIM);
    init_invf_kernel<<<1, 64>>>();
    rope_table_kernel<<<SEQ, 64>>>();

    rmsnorm_kernel<<<SEQ, 256>>>(x, ln1, h1);

    // projections: q = h1@Wq ; k = h1@Wk ; v = h1@Wv then vT = v^T (tf32)
    mma_gemm<0, false, false><<<dim3(16, 16, 1), 256, GEMM_SMEM>>>(
        h1, WqT, q, nullptr, DIM, DIM, DIM, DIM, 0, 0, 0, 1, 0.f);
    mma_gemm<0, false, false><<<dim3(4, 16, 1), 256, GEMM_SMEM>>>(
        h1, WkT, k, nullptr, DIM, DIM, DIM, 512, 0, 0, 0, 1, 0.f);
    mma_gemm<0, false, false><<<dim3(4, 16, 1), 256, GEMM_SMEM>>>(
        h1, WvT, v, nullptr, DIM, DIM, DIM, 512, 0, 0, 0, 1, 0.f);
    transpose_round<<<dim3(512 / 32, SEQ / 32), 256>>>(v, vT, SEQ, 512);

    rope_apply_kernel<<<dim3(SEQ, NH + NKV), 64>>>(q, k);

    // scores = causal(q @ k^T) * iscale     [per head]
    mma_gemm<2, true, false><<<dim3(16, 16, NH), 256, GEMM_SMEM>>>(
        q, k, sc, nullptr, HD, DIM, 512, SEQ,
        HD, HD, (long)SEQ * SEQ, NKV, iscale);

    softmax_kernel<<<dim3(SEQ, NH), 256>>>(sc);

    // at = probs @ v   (K truncated causally, tf32-rounded out)
    mma_gemm<4, false, true><<<dim3(1, 16, NH), 256, GEMM_SMEM>>>(
        sc, vT, at, nullptr, SEQ, SEQ, SEQ, DIM,
        (long)SEQ * SEQ, (long)HD * SEQ, HD, NKV, 0.f);

    // x2 = at @ Wo + x
    mma_gemm<1, false, false><<<dim3(16, 16, 1), 256, GEMM_SMEM>>>(
        at, WoT, x2, x, DIM, DIM, DIM, DIM, 0, 0, 0, 1, 0.f);

    rmsnorm_kernel<<<SEQ, 256>>>(x2, ln2, h2);

    // gg = h2@Wg ; mm = tf32(silu(gg) * (h2@Wu)) ; out = mm@Wd + x2
    mma_gemm<0, false, false><<<dim3(64, 16, 1), 256, GEMM_SMEM>>>(
        h2, WgT, gg, nullptr, DIM, DIM, DIM, FF, 0, 0, 0, 1, 0.f);
    mma_gemm<3, false, false><<<dim3(64, 16, 1), 256, GEMM_SMEM>>>(
        h2, WuT, mm, gg, DIM, DIM, DIM, FF, 0, 0, 0, 1, 0.f);
    mma_gemm<1, false, false><<<dim3(16, 16, 1), 256, GEMM_SMEM>>>(
        mm, WdT, out, x2, FF, FF, FF, DIM, 0, 0, 0, 1, 0.f);
}

// round 5
// speedup vs baseline: 4.1286x; 1.0798x over previous
#include <cuda_runtime.h>
#include <cstdint>
#include <math.h>

constexpr int SEQ = 2048, DIM = 2048, NH = 16, NKV = 4, HD = 128, FF = 8192;
constexpr float EPSV = 1e-6f;

// ---------------------------------------------------------------------------
// Scratch (device globals — allocation forbidden)
// ---------------------------------------------------------------------------
__device__ float g_h1[SEQ * DIM];
__device__ float g_q [SEQ * NH * HD];
__device__ float g_k [SEQ * NKV * HD];
__device__ float g_v [SEQ * NKV * HD];
__device__ float g_vT[NKV * HD * SEQ];
__device__ float g_sc[(long)NH * SEQ * SEQ];
__device__ float g_at[SEQ * NH * HD];
__device__ float g_x2[SEQ * DIM];
__device__ float g_h2[SEQ * DIM];
__device__ float g_gg[(long)SEQ * FF];
__device__ float g_mm[(long)SEQ * FF];
__device__ float g_WqT[DIM * DIM];
__device__ float g_WkT[NKV * HD * DIM];
__device__ float g_WvT[NKV * HD * DIM];
__device__ float g_WoT[DIM * DIM];
__device__ float g_WgT[(long)FF * DIM];
__device__ float g_WuT[(long)FF * DIM];
__device__ float g_WdT[(long)DIM * FF];
__device__ double g_invf[64];
__device__ float2 g_cs[SEQ * 64];

// ---------------------------------------------------------------------------
__device__ __forceinline__ uint32_t smem_u32(const void* p) {
    uint32_t a;
    asm("{ .reg .u64 t; cvta.to.shared.u64 t, %1; cvt.u32.u64 %0, t; }" : "=r"(a) : "l"(p));
    return a;
}
__device__ __forceinline__ float to_tf32(float x) {
    uint32_t u;
    asm("cvt.rna.tf32.f32 %0, %1;" : "=r"(u) : "f"(x));
    return __uint_as_float(u);
}
__device__ __forceinline__ void cp16(uint32_t dst, const void* src) {
    asm volatile("cp.async.cg.shared.global [%0], [%1], 16;" :: "r"(dst), "l"(src) : "memory");
}
__device__ __forceinline__ void cp_commit() {
    asm volatile("cp.async.commit_group;" ::: "memory");
}
template<int N> __device__ __forceinline__ void cp_wait() {
    asm volatile("cp.async.wait_group %0;" :: "n"(N) : "memory");
}
__device__ __forceinline__ void mma_tf32(float* c, const uint32_t* a, const uint32_t* b) {
    asm volatile(
        "mma.sync.aligned.m16n8k8.row.col.f32.tf32.tf32.f32 "
        "{%0,%1,%2,%3}, {%4,%5,%6,%7}, {%8,%9}, {%0,%1,%2,%3};"
        : "+f"(c[0]), "+f"(c[1]), "+f"(c[2]), "+f"(c[3])
        : "r"(a[0]), "r"(a[1]), "r"(a[2]), "r"(a[3]), "r"(b[0]), "r"(b[1]));
}
__device__ __forceinline__ void ldsm_x4(uint32_t* r, uint32_t addr) {
    asm volatile("ldmatrix.sync.aligned.m8n8.x4.shared.b16 {%0,%1,%2,%3}, [%4];"
                 : "=r"(r[0]), "=r"(r[1]), "=r"(r[2]), "=r"(r[3]) : "r"(addr));
}

__device__ __forceinline__ float fexp(float x) {  // accurate for x <= 0
    float t = x * 1.4426950408889634f;
    float r = rintf(t), f = t - r;
    int i = (int)r;
    float p = 0.0013333558f;
    p = fmaf(p, f, 0.0096181291f);
    p = fmaf(p, f, 0.0555041087f);
    p = fmaf(p, f, 0.2402264476f);
    p = fmaf(p, f, 0.6931471806f);
    p = fmaf(p, f, 1.0f);
    float s = __int_as_float((i + 127) << 23);
    return (x < -80.f) ? 0.f : p * s;
}
__device__ __forceinline__ float silu(float g) {
    float t = fexp(-fabsf(g));
    float s = (g >= 0.f) ? 1.f / (1.f + t) : t / (1.f + t);
    return g * s;
}

// ---------------- transpose + round to tf32: out[N,K] = rna(in[K,N]^T) -----
__global__ __launch_bounds__(256)
void transpose_round(const float* __restrict__ in, float* __restrict__ out, int K, int N) {
    __shared__ float tb[32][33];
    const int kb = blockIdx.y * 32, nb = blockIdx.x * 32;
    const int tx = threadIdx.x & 31, ty4 = threadIdx.x >> 5;
#pragma unroll
    for (int i = 0; i < 4; i++) {
        int r = ty4 * 4 + i;
        tb[r][tx] = to_tf32(in[(size_t)(kb + r) * N + nb + tx]);
    }
    __syncthreads();
#pragma unroll
    for (int i = 0; i < 4; i++) {
        int r = ty4 * 4 + i;
        out[(size_t)(nb + r) * K + kb + tx] = tb[tx][r];
    }
}

// ---------------- rmsnorm (tf32-rounded out) -------------------------------
__global__ __launch_bounds__(256)
void rmsnorm_kernel(const float* __restrict__ x, const float* __restrict__ w,
                    float* __restrict__ o) {
    const int row = blockIdx.x;
    const float* xr = x + (size_t)row * DIM;
    float s = 0.f;
    for (int j = threadIdx.x; j < DIM; j += 256) { float v = xr[j]; s += v * v; }
    __shared__ float red[256];
    red[threadIdx.x] = s;
    __syncthreads();
    for (int st = 128; st > 0; st >>= 1) {
        if (threadIdx.x < st) red[threadIdx.x] += red[threadIdx.x + st];
        __syncthreads();
    }
    const float inv = rsqrtf(red[0] * (1.0f / DIM) + EPSV);
    float* orow = o + (size_t)row * DIM;
    for (int j = threadIdx.x; j < DIM; j += 256)
        orow[j] = to_tf32(xr[j] * inv * w[j]);
}

// ---------------- RoPE -----------------------------------------------------
__global__ void init_invf_kernel() { g_invf[threadIdx.x] = pow(10000.0, -(double)threadIdx.x / 64.0); }
__global__ void rope_table_kernel() {
    int s = blockIdx.x, d = threadIdx.x;
    double ang = (double)s * g_invf[d];
    const double twopi = 6.283185307179586476925287;
    double r = ang - twopi * floor(ang / twopi + 0.5);
    float rf = (float)r;
    g_cs[s * 64 + d] = make_float2(cosf(rf), sinf(rf));
}
__global__ void rope_apply_kernel(float* __restrict__ q, float* __restrict__ k) {
    const int s = blockIdx.x, h = blockIdx.y, d = threadIdx.x;
    float* base = (h < NH) ? (q + (size_t)s * (NH * HD) + h * HD)
                           : (k + (size_t)s * (NKV * HD) + (h - NH) * HD);
    float2 cs = g_cs[s * 64 + d];
    float x0 = base[d], x1 = base[d + 64];
    base[d]      = to_tf32(x0 * cs.x - x1 * cs.y);
    base[d + 64] = to_tf32(x1 * cs.x + x0 * cs.y);
}

// ---------------- softmax (tf32 probs, zero-pad to 128 boundary) -----------
__global__ __launch_bounds__(256)
void softmax_kernel(float* __restrict__ scores) {
    const int srow = blockIdx.x, h = blockIdx.y;
    float* row = scores + ((size_t)h * SEQ + srow) * SEQ;
    const int n = srow + 1;
    const int padn = ((n + 127) / 128) * 128;
    __shared__ float buf[SEQ];
    __shared__ float red[256];
    const int tid = threadIdx.x;
    float mx = -1e30f;
    for (int j = tid; j < n; j += 256) { float v = row[j]; buf[j] = v; mx = fmaxf(mx, v); }
    red[tid] = mx;
    __syncthreads();
    for (int st = 128; st > 0; st >>= 1) {
        if (tid < st) red[tid] = fmaxf(red[tid], red[tid + st]);
        __syncthreads();
    }
    mx = red[0];
    __syncthreads();
    float sum = 0.f;
    for (int j = tid; j < n; j += 256) { float e = fexp(buf[j] - mx); buf[j] = e; sum += e; }
    red[tid] = sum;
    __syncthreads();
    for (int st = 128; st > 0; st >>= 1) {
        if (tid < st) red[tid] += red[tid + st];
        __syncthreads();
    }
    const float inv = 1.0f / red[0];
    for (int j = tid; j < padn; j += 256)
        row[j] = (j < n) ? to_tf32(buf[j] * inv) : 0.0f;
}

// ---------------------------------------------------------------------------
// mma.sync tf32 GEMM with ldmatrix fragment loads.
// C[M,N] = A[M,K] @ B[N,K]^T (both K-major, tf32-rounded).
// BM=128, BN=128, BK=32, 256 threads (8 warps, 2x4), warp tile 64x32.
// EPI: 0 fp32 store, 1 +Aux, 2 *scale causal, 3 tf32(silu(Aux)*acc), 4 tf32.
// ---------------------------------------------------------------------------
constexpr int TS = 36;                    // smem row stride (floats)
constexpr int BUFSZ = 128 * TS;           // one tile buffer (floats)
constexpr int GEMM_SMEM = 4 * BUFSZ * 4;  // A0,A1,B0,B1 bytes (73728)

template<int EPI, bool CAUSAL, bool CK>
__global__ __launch_bounds__(256, 2)
void mma_gemm(const float* __restrict__ A, const float* __restrict__ B,
              float* __restrict__ C, const float* __restrict__ Aux,
              int K, int lda, int ldb, int ldc,
              long zA, long zB, long zC, int bGroup, float scale) {
    const int row0 = blockIdx.y * 128;
    const int col0 = blockIdx.x * 128;
    if (CAUSAL && col0 > row0 + 127) return;
    const int bz = blockIdx.z;
    A += (size_t)bz * zA;
    B += (size_t)(bz / bGroup) * zB;
    C += (size_t)bz * zC;
    if (EPI == 1 || EPI == 3) Aux += (size_t)bz * zC;

    extern __shared__ float sm[];
    const uint32_t smBase = smem_u32(sm);

    const int tid = threadIdx.x;
    const int wid = tid >> 5, lane = tid & 31;
    const int lr = lane >> 2, lc = lane & 3;
    const int wm = (wid & 1) * 64;     // warp row offset in tile
    const int wn = (wid >> 1) * 32;    // warp col offset in tile

    const int nkt = CK ? (row0 + 128) / 32 : K / 32;

    // ldmatrix per-thread row offsets (in floats)
    const int q = lane >> 3, rq = lane & 7;
    const uint32_t aRowOff = (uint32_t)((wm + (q & 1) * 8 + rq) * TS + (q >> 1) * 4);
    const int bHalf = (lane >> 4) & 1, bSub = (lane >> 3) & 1;
    const uint32_t bRowOff = (uint32_t)((wn + bHalf * 8 + rq) * TS + bSub * 4);

    auto stage = [&](int buf, int kt) {
        const float* Ap = A + (size_t)row0 * lda + kt * 32;
        const float* Bp = B + (size_t)col0 * ldb + kt * 32;
        const uint32_t aB = smBase + (uint32_t)buf * BUFSZ * 4;
        const uint32_t bB = smBase + (uint32_t)(2 + buf) * BUFSZ * 4;
#pragma unroll
        for (int j = 0; j < 4; j++) {
            int idx = j * 256 + tid, r = idx >> 3, c4 = idx & 7;
            cp16(aB + (uint32_t)(r * TS + c4 * 4) * 4, Ap + (size_t)r * lda + c4 * 4);
        }
#pragma unroll
        for (int j = 0; j < 4; j++) {
            int idx = j * 256 + tid, r = idx >> 3, c4 = idx & 7;
            cp16(bB + (uint32_t)(r * TS + c4 * 4) * 4, Bp + (size_t)r * ldb + c4 * 4);
        }
    };

    float acc[4][4][4];
#pragma unroll
    for (int mt = 0; mt < 4; mt++)
#pragma unroll
        for (int nt = 0; nt < 4; nt++)
#pragma unroll
            for (int i = 0; i < 4; i++) acc[mt][nt][i] = 0.f;

    stage(0, 0);
    cp_commit();

    for (int kt = 0; kt < nkt; kt++) {
        if (kt + 1 < nkt) { stage((kt + 1) & 1, kt + 1); cp_commit(); cp_wait<1>(); }
        else              { cp_wait<0>(); }
        __syncthreads();

        const uint32_t aB4 = smBase + (uint32_t)(kt & 1) * BUFSZ * 4;
        const uint32_t bB4 = smBase + (uint32_t)(2 + (kt & 1)) * BUFSZ * 4;
#pragma unroll
        for (int ks = 0; ks < 4; ks++) {
            uint32_t af[4][4], bf[4][2];
#pragma unroll
            for (int mt = 0; mt < 4; mt++)
                ldsm_x4(af[mt], aB4 + (aRowOff + (uint32_t)(mt * 16 * TS + ks * 8)) * 4);
#pragma unroll
            for (int ntp = 0; ntp < 2; ntp++) {
                uint32_t tmp[4];
                ldsm_x4(tmp, bB4 + (bRowOff + (uint32_t)(ntp * 16 * TS + ks * 8)) * 4);
                bf[ntp * 2][0] = tmp[0]; bf[ntp * 2][1] = tmp[1];
                bf[ntp * 2 + 1][0] = tmp[2]; bf[ntp * 2 + 1][1] = tmp[3];
            }
#pragma unroll
            for (int mt = 0; mt < 4; mt++)
#pragma unroll
                for (int nt = 0; nt < 4; nt++)
                    mma_tf32(acc[mt][nt], af[mt], bf[nt]);
        }
        __syncthreads();
    }

    // -------- epilogue
#pragma unroll
    for (int mt = 0; mt < 4; mt++) {
        const int ra = row0 + wm + mt * 16 + lr;
        const int rb = ra + 8;
#pragma unroll
        for (int nt = 0; nt < 4; nt++) {
            const int c = col0 + wn + nt * 8 + lc * 2;
            float* acc4 = acc[mt][nt];
            const size_t ia = (size_t)ra * ldc + c;
            const size_t ib = (size_t)rb * ldc + c;
            if (EPI == 0) {
                *(float2*)&C[ia] = make_float2(acc4[0], acc4[1]);
                *(float2*)&C[ib] = make_float2(acc4[2], acc4[3]);
            } else if (EPI == 1) {
                float2 xa = *(const float2*)&Aux[ia], xb = *(const float2*)&Aux[ib];
                *(float2*)&C[ia] = make_float2(acc4[0] + xa.x, acc4[1] + xa.y);
                *(float2*)&C[ib] = make_float2(acc4[2] + xb.x, acc4[3] + xb.y);
            } else if (EPI == 2) {
                if (c     <= ra) C[ia]     = acc4[0] * scale;
                if (c + 1 <= ra) C[ia + 1] = acc4[1] * scale;
                if (c     <= rb) C[ib]     = acc4[2] * scale;
                if (c + 1 <= rb) C[ib + 1] = acc4[3] * scale;
            } else if (EPI == 3) {
                float2 ga = *(const float2*)&Aux[ia], gb = *(const float2*)&Aux[ib];
                *(float2*)&C[ia] = make_float2(to_tf32(acc4[0] * silu(ga.x)),
                                               to_tf32(acc4[1] * silu(ga.y)));
                *(float2*)&C[ib] = make_float2(to_tf32(acc4[2] * silu(gb.x)),
                                               to_tf32(acc4[3] * silu(gb.y)));
            } else {  // EPI == 4
                *(float2*)&C[ia] = make_float2(to_tf32(acc4[0]), to_tf32(acc4[1]));
                *(float2*)&C[ib] = make_float2(to_tf32(acc4[2]), to_tf32(acc4[3]));
            }
        }
    }
}

// ---------------------------------------------------------------------------
extern "C" void kernel_launch(void* const* d_in, const int* in_sizes, int n_in,
                              void* d_out, int out_size) {
    (void)in_sizes; (void)n_in; (void)out_size;
    const float* x   = (const float*)d_in[0];
    const float* ln1 = (const float*)d_in[2];
    const float* Wq  = (const float*)d_in[3];
    const float* Wk  = (const float*)d_in[4];
    const float* Wv  = (const float*)d_in[5];
    const float* Wo  = (const float*)d_in[6];
    const float* ln2 = (const float*)d_in[7];
    const float* Wg  = (const float*)d_in[8];
    const float* Wu  = (const float*)d_in[9];
    const float* Wd  = (const float*)d_in[10];
    float* out = (float*)d_out;

    float *h1, *q, *k, *v, *vT, *sc, *at, *x2, *h2, *gg, *mm;
    float *WqT, *WkT, *WvT, *WoT, *WgT, *WuT, *WdT;
    cudaGetSymbolAddress((void**)&h1, g_h1);   cudaGetSymbolAddress((void**)&q, g_q);
    cudaGetSymbolAddress((void**)&k, g_k);     cudaGetSymbolAddress((void**)&v, g_v);
    cudaGetSymbolAddress((void**)&vT, g_vT);   cudaGetSymbolAddress((void**)&sc, g_sc);
    cudaGetSymbolAddress((void**)&at, g_at);   cudaGetSymbolAddress((void**)&x2, g_x2);
    cudaGetSymbolAddress((void**)&h2, g_h2);   cudaGetSymbolAddress((void**)&gg, g_gg);
    cudaGetSymbolAddress((void**)&mm, g_mm);
    cudaGetSymbolAddress((void**)&WqT, g_WqT); cudaGetSymbolAddress((void**)&WkT, g_WkT);
    cudaGetSymbolAddress((void**)&WvT, g_WvT); cudaGetSymbolAddress((void**)&WoT, g_WoT);
    cudaGetSymbolAddress((void**)&WgT, g_WgT); cudaGetSymbolAddress((void**)&WuT, g_WuT);
    cudaGetSymbolAddress((void**)&WdT, g_WdT);

    cudaFuncSetAttribute(mma_gemm<0, false, false>, cudaFuncAttributeMaxDynamicSharedMemorySize, GEMM_SMEM);
    cudaFuncSetAttribute(mma_gemm<1, false, false>, cudaFuncAttributeMaxDynamicSharedMemorySize, GEMM_SMEM);
    cudaFuncSetAttribute(mma_gemm<2, true,  false>, cudaFuncAttributeMaxDynamicSharedMemorySize, GEMM_SMEM);
    cudaFuncSetAttribute(mma_gemm<3, false, false>, cudaFuncAttributeMaxDynamicSharedMemorySize, GEMM_SMEM);
    cudaFuncSetAttribute(mma_gemm<4, false, true >, cudaFuncAttributeMaxDynamicSharedMemorySize, GEMM_SMEM);

    const float iscale = 0.08838834764831843f;  // 1/sqrt(128)

    transpose_round<<<dim3(DIM / 32, DIM / 32), 256>>>(Wq, WqT, DIM, DIM);
    transpose_round<<<dim3(512 / 32, DIM / 32), 256>>>(Wk, WkT, DIM, 512);
    transpose_round<<<dim3(512 / 32, DIM / 32), 256>>>(Wv, WvT, DIM, 512);
    transpose_round<<<dim3(DIM / 32, DIM / 32), 256>>>(Wo, WoT, DIM, DIM);
    transpose_round<<<dim3(FF / 32, DIM / 32), 256>>>(Wg, WgT, DIM, FF);
    transpose_round<<<dim3(FF / 32, DIM / 32), 256>>>(Wu, WuT, DIM, FF);
    transpose_round<<<dim3(DIM / 32, FF / 32), 256>>>(Wd, WdT, FF, DIM);
    init_invf_kernel<<<1, 64>>>();
    rope_table_kernel<<<SEQ, 64>>>();

    rmsnorm_kernel<<<SEQ, 256>>>(x, ln1, h1);

    mma_gemm<0, false, false><<<dim3(16, 16, 1), 256, GEMM_SMEM>>>(
        h1, WqT, q, nullptr, DIM, DIM, DIM, DIM, 0, 0, 0, 1, 0.f);
    mma_gemm<0, false, false><<<dim3(4, 16, 1), 256, GEMM_SMEM>>>(
        h1, WkT, k, nullptr, DIM, DIM, DIM, 512, 0, 0, 0, 1, 0.f);
    mma_gemm<0, false, false><<<dim3(4, 16, 1), 256, GEMM_SMEM>>>(
        h1, WvT, v, nullptr, DIM, DIM, DIM, 512, 0, 0, 0, 1, 0.f);
    transpose_round<<<dim3(512 / 32, SEQ / 32), 256>>>(v, vT, SEQ, 512);

    rope_apply_kernel<<<dim3(SEQ, NH + NKV), 64>>>(q, k);

    mma_gemm<2, true, false><<<dim3(16, 16, NH), 256, GEMM_SMEM>>>(
        q, k, sc, nullptr, HD, DIM, 512, SEQ,
        HD, HD, (long)SEQ * SEQ, NKV, iscale);

    softmax_kernel<<<dim3(SEQ, NH), 256>>>(sc);

    mma_gemm<4, false, true><<<dim3(1, 16, NH), 256, GEMM_SMEM>>>(
        sc, vT, at, nullptr, SEQ, SEQ, SEQ, DIM,
        (long)SEQ * SEQ, (long)HD * SEQ, HD, NKV, 0.f);

    mma_gemm<1, false, false><<<dim3(16, 16, 1), 256, GEMM_SMEM>>>(
        at, WoT, x2, x, DIM, DIM, DIM, DIM, 0, 0, 0, 1, 0.f);

    rmsnorm_kernel<<<SEQ, 256>>>(x2, ln2, h2);

    mma_gemm<0, false, false><<<dim3(64, 16, 1), 256, GEMM_SMEM>>>(
        h2, WgT, gg, nullptr, DIM, DIM, DIM, FF, 0, 0, 0, 1, 0.f);
    mma_gemm<3, false, false><<<dim3(64, 16, 1), 256, GEMM_SMEM>>>(
        h2, WuT, mm, gg, DIM, DIM, DIM, FF, 0, 0, 0, 1, 0.f);
    mma_gemm<1, false, false><<<dim3(16, 16, 1), 256, GEMM_SMEM>>>(
        mm, WdT, out, x2, FF, FF, FF, DIM, 0, 0, 0, 1, 0.f);
}